// round 17
// baseline (speedup 1.0000x reference)
#include <cuda_runtime.h>

#define B_    16
#define CIN_  256
#define COUT_ 3
#define WDIM_ 512
#define INS   128
#define OUTS  256
#define FW    13
#define TR    32                  // output rows per upsample tile
#define IRV   22                  // input rows staged per tile (TR/2 + 6)
#define INP   136                 // padded cols: src col -4 .. 131
#define CSPL  4                   // channel splits in einsum
#define CPB   (CIN_ / CSPL)       // 64 channels per block
#define PLN   (INS * INS)         // 16384 px per plane
#define BCP   (B_ * COUT_)        // 48 planes
#define NEIN  (B_ * 32)           // 512 einsum blocks (8 tiles x 4 splits x 16 b)
#define NUP   (BCP * 8)           // 384 upsample blocks

// scratch (allocation-free rule: __device__ globals; zero-initialized at load)
__device__ float        g_part[CSPL * BCP * PLN];   // unclamped partial sums
__device__ unsigned int g_cnt[B_];                  // einsum blocks done per batch
__device__ unsigned int g_done[B_];                 // upfused blocks done per batch

// ---- packed f32x2 helpers ---------------------------------------------------
__device__ __forceinline__ unsigned long long pack2(float lo, float hi) {
    unsigned long long r;
    asm("mov.b64 %0, {%1, %2};" : "=l"(r) : "f"(lo), "f"(hi));
    return r;
}
__device__ __forceinline__ void unpack2(unsigned long long v, float& lo, float& hi) {
    asm("mov.b64 {%0, %1}, %2;" : "=f"(lo), "=f"(hi) : "l"(v));
}
#define FFMA2(acc, a, b) \
    asm("fma.rn.f32x2 %0, %1, %2, %0;" : "+l"(acc) : "l"(a), "l"(b))

// shared memory union: a block is either einsum or upsample
struct SmemEin {
    unsigned long long c2[COUT_ * CPB];
};
struct SmemUp {
    float in_s[IRV][INP];
    float h_s[IRV][OUTS];
    float kf[16];
};
union SmemAll {
    SmemEin e;
    SmemUp  u;
};

// ---------------------------------------------------------------------------
// Fused mega-kernel. bid < NEIN: styles+einsum; else: combine+upsample, gated
// on per-batch counters so it overlaps with later-batch einsum work.
__global__ void __launch_bounds__(512, 2) k_all(
        const float* __restrict__ x,
        const float* __restrict__ w,
        const float* __restrict__ aw,
        const float* __restrict__ abias,
        const float* __restrict__ cw,
        const float* __restrict__ cbias,
        const float* __restrict__ filt,
        float* __restrict__ out) {
    __shared__ __align__(16) SmemAll sm;
    const int bid = blockIdx.x;
    const int tid = threadIdx.x;

    if (bid < NEIN) {
        // ================= EINSUM BLOCK =================
        // batch is the SLOW index -> batch b complete early-to-late in b
        const int b    = bid >> 5;
        const int rem  = bid & 31;
        const int s    = rem & 3;          // channel split
        const int tile = rem >> 2;         // 0..7 pixel tile
        const int lane = tid & 31;
        const int wid  = tid >> 5;         // 0..15

        // ---- phase A: styles for channels [s*64, s*64+64) ----
        {
            const float4* w4 = (const float4*)(w + (size_t)b * WDIM_);
            float4 wv0 = w4[lane];
            float4 wv1 = w4[32 + lane];
            float4 wv2 = w4[64 + lane];
            float4 wv3 = w4[96 + lane];
            #pragma unroll
            for (int c8 = 0; c8 < 4; c8++) {
                const int i  = s * CPB + wid * 4 + c8;   // global channel
                const float4* a4 = (const float4*)(aw + (size_t)i * WDIM_);
                float4 av0 = a4[lane];
                float4 av1 = a4[32 + lane];
                float4 av2 = a4[64 + lane];
                float4 av3 = a4[96 + lane];
                float sacc = av0.x * wv0.x + av0.y * wv0.y + av0.z * wv0.z + av0.w * wv0.w
                           + av1.x * wv1.x + av1.y * wv1.y + av1.z * wv1.z + av1.w * wv1.w
                           + av2.x * wv2.x + av2.y * wv2.y + av2.z * wv2.z + av2.w * wv2.w
                           + av3.x * wv3.x + av3.y * wv3.y + av3.z * wv3.z + av3.w * wv3.w;
                #pragma unroll
                for (int off = 16; off; off >>= 1)
                    sacc += __shfl_xor_sync(0xffffffffu, sacc, off);
                if (lane == 0) {
                    float style = (sacc * 0.04419417382415922f /*1/sqrt(512)*/
                                   + abias[i]) * 0.0625f /*1/sqrt(256)*/;
                    const int j = wid * 4 + c8;          // local channel 0..63
                    #pragma unroll
                    for (int o = 0; o < COUT_; o++) {
                        float v = cw[o * CIN_ + i] * style;
                        sm.e.c2[o * CPB + j] = pack2(v, v);
                    }
                }
            }
        }
        __syncthreads();

        // ---- phase B: streaming channel reduction ----
        const int base = tile * 2048 + tid * 4;

        unsigned long long a00 = 0ull, a01 = 0ull;
        unsigned long long a10 = 0ull, a11 = 0ull;
        unsigned long long a20 = 0ull, a21 = 0ull;

        const float* xb = x + ((size_t)b * CIN_ + s * CPB) * PLN + base;
        #pragma unroll 8
        for (int j = 0; j < CPB; j++) {
            float4 v = __ldcs((const float4*)(xb + (size_t)j * PLN));
            unsigned long long vlo = pack2(v.x, v.y);
            unsigned long long vhi = pack2(v.z, v.w);
            unsigned long long c0 = sm.e.c2[j];
            unsigned long long c1 = sm.e.c2[CPB + j];
            unsigned long long ck = sm.e.c2[2 * CPB + j];
            FFMA2(a00, c0, vlo); FFMA2(a01, c0, vhi);
            FFMA2(a10, c1, vlo); FFMA2(a11, c1, vhi);
            FFMA2(a20, ck, vlo); FFMA2(a21, ck, vhi);
        }

        unsigned long long alo[3] = {a00, a10, a20};
        unsigned long long ahi[3] = {a01, a11, a21};
        #pragma unroll
        for (int o = 0; o < COUT_; o++) {
            float4 r;
            unpack2(alo[o], r.x, r.y);
            unpack2(ahi[o], r.z, r.w);
            *(float4*)(g_part + ((size_t)(s * BCP + b * COUT_ + o)) * PLN + base) = r;
        }

        // ---- publish: all writes visible before counter bump ----
        __threadfence();
        __syncthreads();
        if (tid == 0) atomicAdd(&g_cnt[b], 1u);

    } else {
        // ================= UPSAMPLE BLOCK =================
        const int u     = bid - NEIN;
        const int b     = u / 24;            // 24 up-blocks per batch
        const int rem   = u - b * 24;
        const int o     = rem % 3;
        const int tile  = rem / 3;           // 0..7
        const int plane = b * COUT_ + o;
        const int r0    = tile * TR;         // first output row (even)
        const int s0    = r0 >> 1;           // first "center" input row
        const float bia = cbias[o];

        if (tid < FW) sm.u.kf[tid] = 2.0f * filt[FW - 1 - tid];

        // wait for all 32 einsum blocks of this batch
        if (tid == 0) {
            while (__ldcg(&g_cnt[b]) < 32u) __nanosleep(200);
            __threadfence();
        }
        __syncthreads();

        // ---- stage rows s0-3 .. s0+18 with column padding; combine 4 partials
        const float* pp = g_part + (size_t)plane * PLN;
        for (int idx = tid; idx < IRV * (INP / 4); idx += 512) {
            int r  = idx / (INP / 4);          // 0..21
            int c4 = idx - r * (INP / 4);      // 0..33 ; src col = -4 + c4*4
            int gr = s0 - 3 + r;
            float4 v = make_float4(0.f, 0.f, 0.f, 0.f);
            if (gr >= 0 && gr < INS && c4 >= 1 && c4 <= 32) {
                size_t off = (size_t)gr * INS + (c4 - 1) * 4;
                float4 p0 = *(const float4*)(pp + off);
                float4 p1 = *(const float4*)(pp + 1 * (size_t)BCP * PLN + off);
                float4 p2 = *(const float4*)(pp + 2 * (size_t)BCP * PLN + off);
                float4 p3 = *(const float4*)(pp + 3 * (size_t)BCP * PLN + off);
                v.x = fminf(fmaxf(p0.x + p1.x + p2.x + p3.x + bia, -256.f), 256.f);
                v.y = fminf(fmaxf(p0.y + p1.y + p2.y + p3.y + bia, -256.f), 256.f);
                v.z = fminf(fmaxf(p0.z + p1.z + p2.z + p3.z + bia, -256.f), 256.f);
                v.w = fminf(fmaxf(p0.w + p1.w + p2.w + p3.w + bia, -256.f), 256.f);
            }
            *(float4*)&sm.u.in_s[r][c4 * 4] = v;
        }
        __syncthreads();

        // filter taps in registers
        float kfe[6], kfo[7];
        #pragma unroll
        for (int j = 0; j < 6; j++) kfe[j] = sm.u.kf[2 * j + 1];
        #pragma unroll
        for (int j = 0; j < 7; j++) kfo[j] = sm.u.kf[2 * j];

        // ---- horizontal: thread (rg, m) produces output cols 2m, 2m+1 ----
        {
            const int rg = tid >> 7;           // 0..3
            const int m  = tid & 127;          // source col
            for (int r = rg; r < IRV; r += 4) {
                const float* row = &sm.u.in_s[r][m + 1];  // src col m-3
                float v0 = row[0], v1 = row[1], v2 = row[2], v3 = row[3];
                float v4 = row[4], v5 = row[5], v6 = row[6];
                float ev = kfe[0] * v0 + kfe[1] * v1 + kfe[2] * v2
                         + kfe[3] * v3 + kfe[4] * v4 + kfe[5] * v5;
                float od = kfo[0] * v0 + kfo[1] * v1 + kfo[2] * v2
                         + kfo[3] * v3 + kfo[4] * v4 + kfo[5] * v5 + kfo[6] * v6;
                *(float2*)&sm.u.h_s[r][2 * m] = make_float2(ev, od);
            }
        }
        __syncthreads();

        // ---- vertical: half h covers output rows [h*16, h*16+16) ----
        const int col  = tid & 255;
        const int half = tid >> 8;             // 0 or 1
        float hv[14];
        const int vb = half * 8;
        #pragma unroll
        for (int r = 0; r < 14; r++) hv[r] = sm.u.h_s[vb + r][col];

        float* op = out + ((size_t)plane * OUTS + r0 + half * 16) * OUTS + col;
        #pragma unroll
        for (int k = 0; k < 16; k++) {
            const int lrb = k >> 1;
            float acc = 0.f;
            if (k & 1) {
                #pragma unroll
                for (int j = 0; j < 7; j++)
                    acc += kfo[j] * hv[lrb + j];
            } else {
                #pragma unroll
                for (int j = 0; j < 6; j++)
                    acc += kfe[j] * hv[lrb + j];
            }
            op[k * OUTS] = acc;
        }

        // ---- counter reset for graph-replay determinism ----
        __syncthreads();
        if (tid == 0) {
            unsigned int old = atomicAdd(&g_done[b], 1u);
            if (old == 23u) {                 // last up-block of this batch
                atomicExch(&g_cnt[b], 0u);
                atomicExch(&g_done[b], 0u);
            }
        }
    }
}

// ---------------------------------------------------------------------------
extern "C" void kernel_launch(void* const* d_in, const int* in_sizes, int n_in,
                              void* d_out, int out_size) {
    const float* x     = (const float*)d_in[0];  // [16,256,128,128]
    const float* w     = (const float*)d_in[1];  // [16,512]
    const float* aw    = (const float*)d_in[2];  // [256,512]
    const float* ab    = (const float*)d_in[3];  // [256]
    const float* cw    = (const float*)d_in[4];  // [3,256,1,1]
    const float* cb    = (const float*)d_in[5];  // [3]
    const float* filt  = (const float*)d_in[6];  // [13]
    float* out = (float*)d_out;                  // [16,3,256,256]

    k_all<<<NEIN + NUP, 512>>>(x, w, aw, ab, cw, cb, filt, out);
}